// round 2
// baseline (speedup 1.0000x reference)
#include <cuda_runtime.h>

// Problem constants
#define BB   4
#define CC   3
#define HH   1024
#define WW   1024
#define HWN  (HH * WW)          // 1<<20
#define NPIX (BB * HWN)         // 1<<22 = 4,194,304
#define NELEM (BB * CC * HWN)   // 12,582,912

// Scratch: two warped images, channel-last [B,H,W,C] so the 3 channel atomics
// of one corner land in consecutive words (same 128B line).
__device__ float g_warp[2][(size_t)NPIX * CC];

__global__ void zero_kernel(float* __restrict__ out) {
    size_t i = (size_t)blockIdx.x * blockDim.x + threadIdx.x;
    const size_t n4 = (size_t)2 * NPIX * CC / 4;   // 6,291,456 float4s
    float4* p = reinterpret_cast<float4*>(&g_warp[0][0]);
    if (i < n4) p[i] = make_float4(0.f, 0.f, 0.f, 0.f);
    if (i == 0) *out = 0.f;
}

// One thread per (f, b, h, w): f=0 warps im0 with flows[0]/t, f=1 warps im1
// with flows[1]/(1-t). Bilinear scatter-add into g_warp[f].
__global__ void splat_kernel(const float* __restrict__ flows,
                             const float* __restrict__ im0,
                             const float* __restrict__ im1,
                             const float* __restrict__ tval) {
    unsigned idx = blockIdx.x * blockDim.x + threadIdx.x;
    if (idx >= 2u * NPIX) return;
    const int      f   = idx >> 22;
    const unsigned rem = idx & (NPIX - 1);
    const int      b   = rem >> 20;
    const unsigned p   = rem & (HWN - 1);
    const int      h   = p >> 10;
    const int      w   = p & (WW - 1);

    const float t = tval[b];
    const float s = f ? (1.0f / (1.0f - t)) : (1.0f / t);

    const float* fb = flows + ((size_t)(f * BB + b) * 2) * HWN;
    const float X = (float)w + s * fb[p];
    const float Y = (float)h + s * fb[HWN + p];

    const float x0f = floorf(X), y0f = floorf(Y);
    const int   x0 = (int)x0f,  y0 = (int)y0f;
    const float fx = X - x0f,   fy = Y - y0f;

    const float* im = f ? im1 : im0;
    const float v0 = im[((size_t)b * CC + 0) * HWN + p];
    const float v1 = im[((size_t)b * CC + 1) * HWN + p];
    const float v2 = im[((size_t)b * CC + 2) * HWN + p];

    float* wp = g_warp[f];
    #pragma unroll
    for (int dy = 0; dy < 2; dy++) {
        const int y = y0 + dy;
        if ((unsigned)y >= (unsigned)HH) continue;
        const float wy = dy ? fy : (1.0f - fy);
        #pragma unroll
        for (int dx = 0; dx < 2; dx++) {
            const int x = x0 + dx;
            if ((unsigned)x >= (unsigned)WW) continue;
            const float wt = wy * (dx ? fx : (1.0f - fx));
            float* dst = wp + (size_t)(((b * HH + y) * WW) + x) * CC;
            atomicAdd(dst + 0, wt * v0);
            atomicAdd(dst + 1, wt * v1);
            atomicAdd(dst + 2, wt * v2);
        }
    }
}

// loss = mean|warp0 - im1| + mean|warp1 - im0|  (each mean over NELEM)
__global__ void loss_kernel(const float* __restrict__ im0,
                            const float* __restrict__ im1,
                            float* __restrict__ out) {
    float acc = 0.f;
    const unsigned stride = gridDim.x * blockDim.x;
    for (unsigned i = blockIdx.x * blockDim.x + threadIdx.x; i < NPIX; i += stride) {
        const int      b = i >> 20;
        const unsigned p = i & (HWN - 1);
        const float* w0 = g_warp[0] + (size_t)i * CC;
        const float* w1 = g_warp[1] + (size_t)i * CC;
        #pragma unroll
        for (int c = 0; c < CC; c++) {
            const float a0 = im1[((size_t)b * CC + c) * HWN + p];
            const float a1 = im0[((size_t)b * CC + c) * HWN + p];
            acc += fabsf(w0[c] - a0) + fabsf(w1[c] - a1);
        }
    }
    // intra-warp reduce
    #pragma unroll
    for (int o = 16; o; o >>= 1) acc += __shfl_down_sync(0xffffffffu, acc, o);
    __shared__ float sb[32];
    const int lane = threadIdx.x & 31, wid = threadIdx.x >> 5;
    if (lane == 0) sb[wid] = acc;
    __syncthreads();
    if (wid == 0) {
        acc = (lane < (int)(blockDim.x >> 5)) ? sb[lane] : 0.f;
        #pragma unroll
        for (int o = 16; o; o >>= 1) acc += __shfl_down_sync(0xffffffffu, acc, o);
        if (lane == 0) atomicAdd(out, acc * (1.0f / (float)NELEM));
    }
}

extern "C" void kernel_launch(void* const* d_in, const int* in_sizes, int n_in,
                              void* d_out, int out_size) {
    const float* flows = (const float*)d_in[0];   // [2,B,2,H,W]
    const float* im0   = (const float*)d_in[1];   // [B,C,H,W]
    const float* im1   = (const float*)d_in[2];   // [B,C,H,W]
    const float* tval  = (const float*)d_in[3];   // [B]
    float* out = (float*)d_out;

    {
        const size_t n4 = (size_t)2 * NPIX * CC / 4;
        const int threads = 256;
        const int blocks = (int)((n4 + threads - 1) / threads);
        zero_kernel<<<blocks, threads>>>(out);
    }
    {
        const int threads = 256;
        const int blocks = (2 * NPIX + threads - 1) / threads;  // 32768
        splat_kernel<<<blocks, threads>>>(flows, im0, im1, tval);
    }
    {
        const int threads = 256;
        const int blocks = 148 * 8;   // grid-stride over 4M pixels
        loss_kernel<<<blocks, threads>>>(im0, im1, out);
    }
}

// round 3
// speedup vs baseline: 1.9968x; 1.9968x over previous
#include <cuda_runtime.h>

// Problem constants
#define BB   4
#define CC   3
#define CP   4                  // padded channels (16B per pixel)
#define HH   1024
#define WW   1024
#define HWN  (HH * WW)          // 1<<20
#define NPIX (BB * HWN)         // 1<<22 = 4,194,304
#define NELEM (BB * CC * HWN)   // 12,582,912

// Scratch: two warped images, channel-last padded [B,H,W,4] so each corner's
// channel accumulation is a single 16B red.global.add.v4.f32.
__device__ float g_warp[2][(size_t)NPIX * CP];

__global__ void zero_kernel(float* __restrict__ out) {
    size_t i = (size_t)blockIdx.x * blockDim.x + threadIdx.x;
    const size_t n4 = (size_t)2 * NPIX;   // 8,388,608 float4s
    float4* p = reinterpret_cast<float4*>(&g_warp[0][0]);
    if (i < n4) p[i] = make_float4(0.f, 0.f, 0.f, 0.f);
    if (i == 0) *out = 0.f;
}

__device__ __forceinline__ void red_v4(float* ptr, float a, float b, float c) {
    asm volatile("red.global.add.v4.f32 [%0], {%1, %2, %3, %4};"
                 :: "l"(ptr), "f"(a), "f"(b), "f"(c), "f"(0.0f) : "memory");
}

// One thread per (f, b, h, w): f=0 warps im0 with flows[0]/t, f=1 warps im1
// with flows[1]/(1-t). Bilinear scatter-add into g_warp[f].
__global__ void splat_kernel(const float* __restrict__ flows,
                             const float* __restrict__ im0,
                             const float* __restrict__ im1,
                             const float* __restrict__ tval) {
    unsigned idx = blockIdx.x * blockDim.x + threadIdx.x;
    if (idx >= 2u * NPIX) return;
    const int      f   = idx >> 22;
    const unsigned rem = idx & (NPIX - 1);
    const int      b   = rem >> 20;
    const unsigned p   = rem & (HWN - 1);
    const int      h   = p >> 10;
    const int      w   = p & (WW - 1);

    const float t = tval[b];
    const float s = f ? (1.0f / (1.0f - t)) : (1.0f / t);

    const float* fb = flows + ((size_t)(f * BB + b) * 2) * HWN;
    const float X = (float)w + s * fb[p];
    const float Y = (float)h + s * fb[HWN + p];

    const float x0f = floorf(X), y0f = floorf(Y);
    const int   x0 = (int)x0f,  y0 = (int)y0f;
    const float fx = X - x0f,   fy = Y - y0f;

    const float* im = f ? im1 : im0;
    const float v0 = im[((size_t)b * CC + 0) * HWN + p];
    const float v1 = im[((size_t)b * CC + 1) * HWN + p];
    const float v2 = im[((size_t)b * CC + 2) * HWN + p];

    float* wp = g_warp[f];
    #pragma unroll
    for (int dy = 0; dy < 2; dy++) {
        const int y = y0 + dy;
        if ((unsigned)y >= (unsigned)HH) continue;
        const float wy = dy ? fy : (1.0f - fy);
        #pragma unroll
        for (int dx = 0; dx < 2; dx++) {
            const int x = x0 + dx;
            if ((unsigned)x >= (unsigned)WW) continue;
            const float wt = wy * (dx ? fx : (1.0f - fx));
            float* dst = wp + (size_t)(((b * HH + y) * WW) + x) * CP;
            red_v4(dst, wt * v0, wt * v1, wt * v2);
        }
    }
}

// loss = mean|warp0 - im1| + mean|warp1 - im0|  (each mean over NELEM)
__global__ void loss_kernel(const float* __restrict__ im0,
                            const float* __restrict__ im1,
                            float* __restrict__ out) {
    float acc = 0.f;
    const unsigned stride = gridDim.x * blockDim.x;
    const float4* w0p = reinterpret_cast<const float4*>(&g_warp[0][0]);
    const float4* w1p = reinterpret_cast<const float4*>(&g_warp[1][0]);
    for (unsigned i = blockIdx.x * blockDim.x + threadIdx.x; i < NPIX; i += stride) {
        const int      b = i >> 20;
        const unsigned p = i & (HWN - 1);
        const float4 w0 = w0p[i];
        const float4 w1 = w1p[i];
        const size_t base = (size_t)b * CC * HWN + p;
        acc += fabsf(w0.x - im1[base]) +
               fabsf(w0.y - im1[base + HWN]) +
               fabsf(w0.z - im1[base + 2 * HWN]);
        acc += fabsf(w1.x - im0[base]) +
               fabsf(w1.y - im0[base + HWN]) +
               fabsf(w1.z - im0[base + 2 * HWN]);
    }
    // intra-warp reduce
    #pragma unroll
    for (int o = 16; o; o >>= 1) acc += __shfl_down_sync(0xffffffffu, acc, o);
    __shared__ float sb[32];
    const int lane = threadIdx.x & 31, wid = threadIdx.x >> 5;
    if (lane == 0) sb[wid] = acc;
    __syncthreads();
    if (wid == 0) {
        acc = (lane < (int)(blockDim.x >> 5)) ? sb[lane] : 0.f;
        #pragma unroll
        for (int o = 16; o; o >>= 1) acc += __shfl_down_sync(0xffffffffu, acc, o);
        if (lane == 0) atomicAdd(out, acc * (1.0f / (float)NELEM));
    }
}

extern "C" void kernel_launch(void* const* d_in, const int* in_sizes, int n_in,
                              void* d_out, int out_size) {
    const float* flows = (const float*)d_in[0];   // [2,B,2,H,W]
    const float* im0   = (const float*)d_in[1];   // [B,C,H,W]
    const float* im1   = (const float*)d_in[2];   // [B,C,H,W]
    const float* tval  = (const float*)d_in[3];   // [B]
    float* out = (float*)d_out;

    {
        const size_t n4 = (size_t)2 * NPIX;
        const int threads = 256;
        const int blocks = (int)((n4 + threads - 1) / threads);
        zero_kernel<<<blocks, threads>>>(out);
    }
    {
        const int threads = 256;
        const int blocks = (2 * NPIX + threads - 1) / threads;  // 32768
        splat_kernel<<<blocks, threads>>>(flows, im0, im1, tval);
    }
    {
        const int threads = 256;
        const int blocks = 148 * 8;   // grid-stride over 4M pixels
        loss_kernel<<<blocks, threads>>>(im0, im1, out);
    }
}

// round 4
// speedup vs baseline: 2.7975x; 1.4010x over previous
#include <cuda_runtime.h>
#include <cuda_fp16.h>

// Problem constants
#define BB   4
#define CC   3
#define HH   1024
#define WW   1024
#define SW   (WW + 4)           // row stride in pixels: 2 guard cols each side
#define HWN  (HH * WW)          // 1<<20
#define NPIX (BB * HWN)         // 1<<22 = 4,194,304
#define NELEM (BB * CC * HWN)   // 12,582,912

// fp16 accumulators, channel-last padded to 4 halves (8B) per pixel, with 2
// guard columns on each side of every row (absorb x0=-1 / x1=W writes).
// Per f: B*H*SW pixels * 4 halves = 33.7 MB; both f = 67.4 MB (L2-resident).
#define ACC_HALVES ((size_t)BB * HH * SW * 4)
__device__ __align__(32) __half g_acc[2][ACC_HALVES];

__global__ void zero_kernel(float* __restrict__ out) {
    size_t i = (size_t)blockIdx.x * blockDim.x + threadIdx.x;
    const size_t n4 = 2 * ACC_HALVES * sizeof(__half) / 16;   // float4 count
    float4* p = reinterpret_cast<float4*>(&g_acc[0][0]);
    if (i < n4) p[i] = make_float4(0.f, 0.f, 0.f, 0.f);
    if (i == 0) *out = 0.f;
}

static __device__ __forceinline__ unsigned pack2(float a, float b) {
    __half2 h = __floats2half2_rn(a, b);
    return *reinterpret_cast<unsigned*>(&h);
}
static __device__ __forceinline__ void red_v4h(__half* p, unsigned a, unsigned b,
                                               unsigned c, unsigned d) {
    asm volatile("red.global.add.noftz.v4.f16x2 [%0], {%1, %2, %3, %4};"
                 :: "l"(p), "r"(a), "r"(b), "r"(c), "r"(d) : "memory");
}
static __device__ __forceinline__ void red_v2h(__half* p, unsigned a, unsigned b) {
    asm volatile("red.global.add.noftz.v2.f16x2 [%0], {%1, %2};"
                 :: "l"(p), "r"(a), "r"(b) : "memory");
}

// One thread per (f, b, h, w): f=0 warps im0 with flows[0]/t, f=1 warps im1
// with flows[1]/(1-t). Bilinear scatter-add into g_acc[f].
__global__ void splat_kernel(const float* __restrict__ flows,
                             const float* __restrict__ im0,
                             const float* __restrict__ im1,
                             const float* __restrict__ tval) {
    unsigned idx = blockIdx.x * blockDim.x + threadIdx.x;
    if (idx >= 2u * NPIX) return;
    const int      f   = idx >> 22;
    const unsigned rem = idx & (NPIX - 1);
    const int      b   = rem >> 20;
    const unsigned p   = rem & (HWN - 1);
    const int      h   = p >> 10;
    const int      w   = p & (WW - 1);

    const float t = tval[b];
    const float s = f ? (1.0f / (1.0f - t)) : (1.0f / t);

    const float* fb = flows + ((size_t)(f * BB + b) * 2) * HWN;
    const float X = (float)w + s * fb[p];
    const float Y = (float)h + s * fb[HWN + p];

    const float x0f = floorf(X), y0f = floorf(Y);
    const int   x0 = (int)x0f,  y0 = (int)y0f;
    const float fx = X - x0f,   fy = Y - y0f;

    if (x0 < -1 || x0 > WW - 1) return;      // no x corner in range
    if (y0 < -1 || y0 > HH - 1) return;      // no y corner in range

    const float* im = f ? im1 : im0;
    const float v0 = im[((size_t)b * CC + 0) * HWN + p];
    const float v1 = im[((size_t)b * CC + 1) * HWN + p];
    const float v2 = im[((size_t)b * CC + 2) * HWN + p];

    __half* base = g_acc[f];
    const bool even = (x0 & 1) == 0;

    #pragma unroll
    for (int r = 0; r < 2; r++) {
        const int y = y0 + r;
        if ((unsigned)y >= (unsigned)HH) continue;
        const float wy = r ? fy : (1.0f - fy);
        const float wa = (1.0f - fx) * wy;    // corner x0
        const float wb = fx * wy;             // corner x0+1
        __half* dst = base + ((size_t)(b * HH + y) * SW + 2 + x0) * 4;
        const unsigned a0 = pack2(wa * v0, wa * v1);
        const unsigned a1 = pack2(wa * v2, 0.0f);
        const unsigned b0 = pack2(wb * v0, wb * v1);
        const unsigned b1 = pack2(wb * v2, 0.0f);
        if (even) {
            red_v4h(dst, a0, a1, b0, b1);       // both corners, one 16B RED
        } else {
            red_v2h(dst, a0, a1);
            red_v2h(dst + 4, b0, b1);
        }
    }
}

// loss = mean|warp0 - im1| + mean|warp1 - im0|  (each mean over NELEM)
__global__ void loss_kernel(const float* __restrict__ im0,
                            const float* __restrict__ im1,
                            float* __restrict__ out) {
    float acc = 0.f;
    const unsigned stride = gridDim.x * blockDim.x;
    for (unsigned i = blockIdx.x * blockDim.x + threadIdx.x; i < NPIX; i += stride) {
        const int      b = i >> 20;
        const unsigned p = i & (HWN - 1);
        const int      y = p >> 10;
        const int      x = p & (WW - 1);
        const size_t pidx = ((size_t)(b * HH + y) * SW + 2 + x) * 4;
        const uint2 u0 = *reinterpret_cast<const uint2*>(&g_acc[0][pidx]);
        const uint2 u1 = *reinterpret_cast<const uint2*>(&g_acc[1][pidx]);
        const float2 w0a = __half22float2(*reinterpret_cast<const __half2*>(&u0.x));
        const float2 w0b = __half22float2(*reinterpret_cast<const __half2*>(&u0.y));
        const float2 w1a = __half22float2(*reinterpret_cast<const __half2*>(&u1.x));
        const float2 w1b = __half22float2(*reinterpret_cast<const __half2*>(&u1.y));
        const size_t base = (size_t)b * CC * HWN + p;
        acc += fabsf(w0a.x - im1[base]) +
               fabsf(w0a.y - im1[base + HWN]) +
               fabsf(w0b.x - im1[base + 2 * HWN]);
        acc += fabsf(w1a.x - im0[base]) +
               fabsf(w1a.y - im0[base + HWN]) +
               fabsf(w1b.x - im0[base + 2 * HWN]);
    }
    // intra-warp reduce
    #pragma unroll
    for (int o = 16; o; o >>= 1) acc += __shfl_down_sync(0xffffffffu, acc, o);
    __shared__ float sb[32];
    const int lane = threadIdx.x & 31, wid = threadIdx.x >> 5;
    if (lane == 0) sb[wid] = acc;
    __syncthreads();
    if (wid == 0) {
        acc = (lane < (int)(blockDim.x >> 5)) ? sb[lane] : 0.f;
        #pragma unroll
        for (int o = 16; o; o >>= 1) acc += __shfl_down_sync(0xffffffffu, acc, o);
        if (lane == 0) atomicAdd(out, acc * (1.0f / (float)NELEM));
    }
}

extern "C" void kernel_launch(void* const* d_in, const int* in_sizes, int n_in,
                              void* d_out, int out_size) {
    const float* flows = (const float*)d_in[0];   // [2,B,2,H,W]
    const float* im0   = (const float*)d_in[1];   // [B,C,H,W]
    const float* im1   = (const float*)d_in[2];   // [B,C,H,W]
    const float* tval  = (const float*)d_in[3];   // [B]
    float* out = (float*)d_out;

    {
        const size_t n4 = 2 * ACC_HALVES * sizeof(__half) / 16;
        const int threads = 256;
        const int blocks = (int)((n4 + threads - 1) / threads);
        zero_kernel<<<blocks, threads>>>(out);
    }
    {
        const int threads = 256;
        const int blocks = (2 * NPIX + threads - 1) / threads;  // 32768
        splat_kernel<<<blocks, threads>>>(flows, im0, im1, tval);
    }
    {
        const int threads = 256;
        const int blocks = 148 * 8;   // grid-stride over 4M pixels
        loss_kernel<<<blocks, threads>>>(im0, im1, out);
    }
}